// round 9
// baseline (speedup 1.0000x reference)
#include <cuda_runtime.h>
#include <cstddef>

// TokenEmbedding segment-sum, GB300 sm_103a — R8: SINGLE fused launch.
// One block per (batch, 4 tokens). Threads 0..4 binary-search the 5 token
// boundaries in the (L1/L2-hot) sorted seg slice and publish via smem; the
// block then streams the contiguous wordpiece range [bnd0, bnd4) with a
// 2-deep load pipeline and routes rows to 4 register accumulators via
// comparisons against the boundary registers (zero in-loop index loads).
// Streaming cache hints (__ldcs/__stcs) for the touch-once bulk data.
// No boundary table, no second kernel, no atomics, no zero-init pass.

constexpr int B = 16;
constexpr int L = 4096;
constexpr int H = 768;
constexpr int V = H / 4;   // 192 float4 per row
constexpr int T = 4;       // tokens per block

__device__ __forceinline__ void accum(float4& a, const float4& v)
{
    a.x += v.x; a.y += v.y; a.z += v.z; a.w += v.w;
}

__device__ __forceinline__ void route(int t, const float4& v,
                                      float4& a0, float4& a1, float4& a2, float4& a3)
{
    if      (t == 0) accum(a0, v);
    else if (t == 1) accum(a1, v);
    else if (t == 2) accum(a2, v);
    else             accum(a3, v);
}

__global__ __launch_bounds__(V) void token_segsum_fused_kernel(
    const float4* __restrict__ x,   // [B, L, V]
    const int*    __restrict__ seg, // [B, L], sorted per batch
    float4*       __restrict__ out) // [B, L, V]
{
    __shared__ int sbnd[T + 1];

    const int b   = blockIdx.y;
    const int j0  = blockIdx.x * T;
    const int col = threadIdx.x;    // 0..191

    // Threads 0..4: lower_bound(seg_b, j0 + t). 12 dependent L1-hot loads,
    // independent chains across the 5 threads; hidden by other resident blocks.
    if (col <= T) {
        const int* __restrict__ s = seg + b * L;
        const int j = j0 + col;
        int lo = 0, hi = L;
        #pragma unroll 1
        while (lo < hi) {
            int mid = (lo + hi) >> 1;
            if (__ldg(s + mid) < j) lo = mid + 1; else hi = mid;
        }
        sbnd[col] = lo;
    }
    __syncthreads();

    const int start = sbnd[0];
    const int b1    = sbnd[1];
    const int b2    = sbnd[2];
    const int b3    = sbnd[3];
    const int end   = sbnd[4];

    const float4* __restrict__ base  = x   + (size_t)b * L * V + col;
    float4*       __restrict__ obase = out + (size_t)b * L * V + (size_t)j0 * V + col;

    float4 a0 = make_float4(0.f, 0.f, 0.f, 0.f);
    float4 a1 = a0, a2 = a0, a3 = a0;

    int p = start;
    #pragma unroll 1
    for (; p + 1 < end; p += 2) {
        // Two independent streaming loads issued before any consumption.
        float4 v0 = __ldcs(base + (size_t)(p + 0) * V);
        float4 v1 = __ldcs(base + (size_t)(p + 1) * V);
        const int t0 = (p + 0 >= b1) + (p + 0 >= b2) + (p + 0 >= b3);
        const int t1 = (p + 1 >= b1) + (p + 1 >= b2) + (p + 1 >= b3);
        route(t0, v0, a0, a1, a2, a3);
        route(t1, v1, a0, a1, a2, a3);
    }
    if (p < end) {
        float4 v0 = __ldcs(base + (size_t)p * V);
        const int t0 = (p >= b1) + (p >= b2) + (p >= b3);
        route(t0, v0, a0, a1, a2, a3);
    }

    __stcs(obase + 0 * V, a0);
    __stcs(obase + 1 * V, a1);
    __stcs(obase + 2 * V, a2);
    __stcs(obase + 3 * V, a3);
}

extern "C" void kernel_launch(void* const* d_in, const int* in_sizes, int n_in,
                              void* d_out, int out_size)
{
    const float4* x   = (const float4*)d_in[0];
    const int*    seg = (const int*)d_in[1];
    float4*       out = (float4*)d_out;

    dim3 grid(L / T, B);
    token_segsum_fused_kernel<<<grid, V>>>(x, seg, out);
}